// round 5
// baseline (speedup 1.0000x reference)
#include <cuda_runtime.h>
#include <cstdint>

#define MAXN 50000
#define MAXE 800000
#define D 64
#define TP 68  // padded smem row (floats); 272 B, multiple of 16

// Scratch (device globals; float4 => 16B alignment for agg)
__device__ int    g_cnt[MAXN];        // per-node in-degree (histogram)
__device__ int    g_off[MAXN + 1];    // CSR offsets
__device__ int    g_cur[MAXN];        // fill cursors
__device__ int    g_scol[MAXE];       // cols sorted by row
__device__ float4 g_agg4[MAXN * (D / 4)];

// ---------------------------------------------------------------------------
// K1: histogram of destination rows
// ---------------------------------------------------------------------------
__global__ void hist_kernel(const int* __restrict__ ei, int E, int N) {
    int e = blockIdx.x * blockDim.x + threadIdx.x;
    if (e < E) {
        int r = min(max(ei[e], 0), N - 1);
        atomicAdd(&g_cnt[r], 1);
    }
}

// ---------------------------------------------------------------------------
// K2: single-block exclusive scan of g_cnt -> g_off / g_cur
// ---------------------------------------------------------------------------
__global__ __launch_bounds__(1024) void scan_kernel(int N) {
    __shared__ int partial[1024];
    const int t = threadIdx.x;
    const int chunk = (N + 1023) / 1024;
    const int beg = t * chunk;
    const int end = min(beg + chunk, N);

    int s = 0;
    for (int i = beg; i < end; i++) s += g_cnt[i];
    partial[t] = s;
    __syncthreads();

    // Hillis-Steele inclusive scan over 1024 partials
    #pragma unroll
    for (int d = 1; d < 1024; d <<= 1) {
        int v = (t >= d) ? partial[t - d] : 0;
        __syncthreads();
        partial[t] += v;
        __syncthreads();
    }

    int run = (t > 0) ? partial[t - 1] : 0;
    for (int i = beg; i < end; i++) {
        g_off[i] = run;
        g_cur[i] = run;
        run += g_cnt[i];
    }
    if (end == N) g_off[N] = run;
}

// ---------------------------------------------------------------------------
// K3: fill CSR column array (bucket by destination row)
// ---------------------------------------------------------------------------
__global__ void fill_kernel(const int* __restrict__ ei, int E, int N) {
    int e = blockIdx.x * blockDim.x + threadIdx.x;
    if (e < E) {
        int r = min(max(ei[e], 0), N - 1);
        int c = min(max(ei[E + e], 0), N - 1);
        int pos = atomicAdd(&g_cur[r], 1);
        g_scol[pos] = c;
    }
}

// ---------------------------------------------------------------------------
// K4: gather-aggregate. One warp per node; lane&15 owns one float4 slot,
// lane>>4 selects one of 2 edges processed per iteration. Pure loads, no
// atomics; fully overwrites g_agg4 (no zero pass needed).
// ---------------------------------------------------------------------------
__global__ __launch_bounds__(256) void gather_kernel(const float* __restrict__ x,
                                                     int N) {
    int warp = (blockIdx.x * blockDim.x + threadIdx.x) >> 5;
    int lane = threadIdx.x & 31;
    if (warp >= N) return;

    const int start = g_off[warp];
    const int end   = g_off[warp + 1];
    const int slot  = lane & 15;
    const int half  = lane >> 4;

    float4 acc = make_float4(0.f, 0.f, 0.f, 0.f);
    for (int e = start + half; e < end; e += 2) {
        int c = g_scol[e];  // same addr across the 16 lanes of a half: L1 broadcast
        float4 v = __ldg(reinterpret_cast<const float4*>(x) + (size_t)c * (D / 4) + slot);
        acc.x += v.x; acc.y += v.y; acc.z += v.z; acc.w += v.w;
    }
    // combine the two halves
    acc.x += __shfl_xor_sync(0xffffffff, acc.x, 16);
    acc.y += __shfl_xor_sync(0xffffffff, acc.y, 16);
    acc.z += __shfl_xor_sync(0xffffffff, acc.z, 16);
    acc.w += __shfl_xor_sync(0xffffffff, acc.w, 16);

    if (half == 0) {
        g_agg4[(size_t)warp * (D / 4) + slot] = acc;
    }
}

// ---------------------------------------------------------------------------
// K5: fused dual GEMM + bias + degree normalization (same as R3 kernel 3).
//   out[n][o] = sum_k x[n][k]*Ws[o][k] + (sum_k agg[n][k]*Wn[o][k])/max(deg,1)
//             + bs[o] + bn[o]
// ---------------------------------------------------------------------------
__global__ __launch_bounds__(256) void sage_gemm_kernel(
    const float* __restrict__ x,
    const float* __restrict__ Ws, const float* __restrict__ bs,
    const float* __restrict__ Wn, const float* __restrict__ bn,
    float* __restrict__ out, int N)
{
    extern __shared__ float sh[];
    float* Wts  = sh;                 // [64][TP]
    float* Wtn  = sh + 64 * TP;       // [64][TP]
    float* xt   = sh + 2 * 64 * TP;   // [64][TP]  (x tile, then agg tile)
    float* bias = sh + 3 * 64 * TP;   // [64]

    const int tid = threadIdx.x;
    const float* agg = reinterpret_cast<const float*>(g_agg4);

    for (int i = tid; i < 64 * 64; i += 256) {
        int o = i >> 6, k = i & 63;
        Wts[k * TP + o] = Ws[i];
        Wtn[k * TP + o] = Wn[i];
    }
    if (tid < 64) bias[tid] = bs[tid] + bn[tid];

    const int to = tid & 15;
    const int tn = tid >> 4;
    const int node0 = blockIdx.x << 6;

    // x tile transposed
    for (int i = tid; i < 64 * 64; i += 256) {
        int n = i >> 6, k = i & 63;
        int node = node0 + n;
        xt[k * TP + n] = (node < N) ? x[(size_t)node * D + k] : 0.f;
    }
    __syncthreads();

    float acc[4][4];
    #pragma unroll
    for (int i = 0; i < 4; i++)
        #pragma unroll
        for (int j = 0; j < 4; j++) acc[i][j] = 0.f;

    #pragma unroll
    for (int k = 0; k < 64; k++) {
        float4 a = *reinterpret_cast<const float4*>(&xt[k * TP + 4 * tn]);
        float4 w = *reinterpret_cast<const float4*>(&Wts[k * TP + 4 * to]);
        float av[4] = {a.x, a.y, a.z, a.w};
        float wv[4] = {w.x, w.y, w.z, w.w};
        #pragma unroll
        for (int i = 0; i < 4; i++)
            #pragma unroll
            for (int j = 0; j < 4; j++) acc[i][j] += av[i] * wv[j];
    }

    __syncthreads();
    // agg tile transposed (reuse xt)
    for (int i = tid; i < 64 * 64; i += 256) {
        int n = i >> 6, k = i & 63;
        int node = node0 + n;
        xt[k * TP + n] = (node < N) ? agg[(size_t)node * D + k] : 0.f;
    }
    __syncthreads();

    float accn[4][4];
    #pragma unroll
    for (int i = 0; i < 4; i++)
        #pragma unroll
        for (int j = 0; j < 4; j++) accn[i][j] = 0.f;

    #pragma unroll
    for (int k = 0; k < 64; k++) {
        float4 a = *reinterpret_cast<const float4*>(&xt[k * TP + 4 * tn]);
        float4 w = *reinterpret_cast<const float4*>(&Wtn[k * TP + 4 * to]);
        float av[4] = {a.x, a.y, a.z, a.w};
        float wv[4] = {w.x, w.y, w.z, w.w};
        #pragma unroll
        for (int i = 0; i < 4; i++)
            #pragma unroll
            for (int j = 0; j < 4; j++) accn[i][j] += av[i] * wv[j];
    }

    float bj[4];
    #pragma unroll
    for (int j = 0; j < 4; j++) bj[j] = bias[4 * to + j];

    #pragma unroll
    for (int i = 0; i < 4; i++) {
        int node = node0 + 4 * tn + i;
        if (node < N) {
            float inv = 1.0f / fmaxf((float)g_cnt[node], 1.0f);
            float4 r;
            r.x = acc[i][0] + accn[i][0] * inv + bj[0];
            r.y = acc[i][1] + accn[i][1] * inv + bj[1];
            r.z = acc[i][2] + accn[i][2] * inv + bj[2];
            r.w = acc[i][3] + accn[i][3] * inv + bj[3];
            *reinterpret_cast<float4*>(&out[(size_t)node * D + 4 * to]) = r;
        }
    }
}

// ---------------------------------------------------------------------------
// Launch
// ---------------------------------------------------------------------------
extern "C" void kernel_launch(void* const* d_in, const int* in_sizes, int n_in,
                              void* d_out, int out_size) {
    const float* x  = (const float*)d_in[0];
    const int*   ei = (const int*)d_in[1];   // int64 reference -> int32 on device
    const float* Ws = (const float*)d_in[2];
    const float* bs = (const float*)d_in[3];
    const float* Wn = (const float*)d_in[4];
    const float* bn = (const float*)d_in[5];
    float*       out = (float*)d_out;

    const int N = in_sizes[0] / D;
    const int E = in_sizes[1] / 2;

    // 0) zero histogram counters (async memset is graph-capturable)
    void* cnt_ptr = nullptr;
    cudaGetSymbolAddress(&cnt_ptr, g_cnt);
    cudaMemsetAsync(cnt_ptr, 0, (size_t)N * sizeof(int));

    // 1) histogram of destination rows
    hist_kernel<<<(E + 255) / 256, 256>>>(ei, E, N);

    // 2) prefix scan -> CSR offsets + cursors
    scan_kernel<<<1, 1024>>>(N);

    // 3) bucket cols by row
    fill_kernel<<<(E + 255) / 256, 256>>>(ei, E, N);

    // 4) gather-aggregate (warp per node)
    {
        int warpsNeeded = N;
        int blocks = (warpsNeeded * 32 + 255) / 256;
        gather_kernel<<<blocks, 256>>>(x, N);
    }

    // 5) fused dual GEMM epilogue
    {
        const int smem = (3 * 64 * TP + 64) * (int)sizeof(float);  // 52480 B
        cudaFuncSetAttribute(sage_gemm_kernel,
                             cudaFuncAttributeMaxDynamicSharedMemorySize, smem);
        int blocks = (N + 63) / 64;
        sage_gemm_kernel<<<blocks, 256, smem>>>(x, Ws, bs, Wn, bn, out, N);
    }
}

// round 6
// speedup vs baseline: 1.8363x; 1.8363x over previous
#include <cuda_runtime.h>
#include <cstdint>

#define MAXN 50000
#define MAXE 800000
#define D 64
#define TP 68  // padded smem row (floats); 272 B, multiple of 16

// Scratch (device globals; float4 => 16B alignment for agg)
__device__ int    g_cnt[MAXN];        // per-node in-degree (histogram)
__device__ int    g_off[MAXN + 1];    // CSR offsets
__device__ int    g_cur[MAXN];        // fill cursors
__device__ int    g_scol[MAXE];       // cols sorted by row
__device__ int    g_blkSum[64];       // per-scan-block sums
__device__ int    g_blkOff[64];       // exclusive-scanned block offsets
__device__ float4 g_agg4[MAXN * (D / 4)];

// ---------------------------------------------------------------------------
// K1: histogram of destination rows
// ---------------------------------------------------------------------------
__global__ void hist_kernel(const int* __restrict__ ei, int E, int N) {
    int e = blockIdx.x * blockDim.x + threadIdx.x;
    if (e < E) {
        int r = min(max(ei[e], 0), N - 1);
        atomicAdd(&g_cnt[r], 1);
    }
}

// ---------------------------------------------------------------------------
// K2a: per-block sums of g_cnt (coalesced, full chip)
// ---------------------------------------------------------------------------
__global__ __launch_bounds__(1024) void scanA_kernel(int N) {
    __shared__ int warpSum[32];
    int i = blockIdx.x * 1024 + threadIdx.x;
    int v = (i < N) ? g_cnt[i] : 0;

    // warp reduce
    #pragma unroll
    for (int d = 16; d > 0; d >>= 1) v += __shfl_xor_sync(0xffffffff, v, d);
    if ((threadIdx.x & 31) == 0) warpSum[threadIdx.x >> 5] = v;
    __syncthreads();
    if (threadIdx.x < 32) {
        int s = warpSum[threadIdx.x];
        #pragma unroll
        for (int d = 16; d > 0; d >>= 1) s += __shfl_xor_sync(0xffffffff, s, d);
        if (threadIdx.x == 0) g_blkSum[blockIdx.x] = s;
    }
}

// ---------------------------------------------------------------------------
// K2b: exclusive scan of the (<=64) block sums, one warp-pair block
// ---------------------------------------------------------------------------
__global__ __launch_bounds__(64) void scanB_kernel(int nb) {
    __shared__ int sh[64];
    int t = threadIdx.x;
    sh[t] = (t < nb) ? g_blkSum[t] : 0;
    __syncthreads();
    #pragma unroll
    for (int d = 1; d < 64; d <<= 1) {
        int v = (t >= d) ? sh[t - d] : 0;
        __syncthreads();
        sh[t] += v;
        __syncthreads();
    }
    if (t < nb) g_blkOff[t] = (t > 0) ? sh[t - 1] : 0;  // exclusive
}

// ---------------------------------------------------------------------------
// K2c: block-local exclusive scan + block offset -> g_off / g_cur (coalesced)
// ---------------------------------------------------------------------------
__global__ __launch_bounds__(1024) void scanC_kernel(int N) {
    __shared__ int sh[1024];
    const int t = threadIdx.x;
    const int i = blockIdx.x * 1024 + t;
    const int v = (i < N) ? g_cnt[i] : 0;
    sh[t] = v;
    __syncthreads();
    #pragma unroll
    for (int d = 1; d < 1024; d <<= 1) {
        int u = (t >= d) ? sh[t - d] : 0;
        __syncthreads();
        sh[t] += u;
        __syncthreads();
    }
    int incl = sh[t] + g_blkOff[blockIdx.x];
    int excl = incl - v;
    if (i < N) {
        g_off[i] = excl;
        g_cur[i] = excl;
        if (i == N - 1) g_off[N] = incl;  // total edge count
    }
}

// ---------------------------------------------------------------------------
// K3: fill CSR column array (bucket by destination row)
// ---------------------------------------------------------------------------
__global__ void fill_kernel(const int* __restrict__ ei, int E, int N) {
    int e = blockIdx.x * blockDim.x + threadIdx.x;
    if (e < E) {
        int r = min(max(ei[e], 0), N - 1);
        int c = min(max(ei[E + e], 0), N - 1);
        int pos = atomicAdd(&g_cur[r], 1);
        g_scol[pos] = c;
    }
}

// ---------------------------------------------------------------------------
// K4: gather-aggregate. One warp per node; lane&15 owns one float4 slot,
// lane>>4 selects one of 2 edges per iteration. Pure loads, no atomics;
// fully overwrites g_agg4. (Measured ~22us: at the L2 bandwidth roofline.)
// ---------------------------------------------------------------------------
__global__ __launch_bounds__(256) void gather_kernel(const float* __restrict__ x,
                                                     int N) {
    int warp = (blockIdx.x * blockDim.x + threadIdx.x) >> 5;
    int lane = threadIdx.x & 31;
    if (warp >= N) return;

    const int start = g_off[warp];
    const int end   = g_off[warp + 1];
    const int slot  = lane & 15;
    const int half  = lane >> 4;

    float4 acc = make_float4(0.f, 0.f, 0.f, 0.f);
    for (int e = start + half; e < end; e += 2) {
        int c = g_scol[e];
        float4 v = __ldg(reinterpret_cast<const float4*>(x) + (size_t)c * (D / 4) + slot);
        acc.x += v.x; acc.y += v.y; acc.z += v.z; acc.w += v.w;
    }
    acc.x += __shfl_xor_sync(0xffffffff, acc.x, 16);
    acc.y += __shfl_xor_sync(0xffffffff, acc.y, 16);
    acc.z += __shfl_xor_sync(0xffffffff, acc.z, 16);
    acc.w += __shfl_xor_sync(0xffffffff, acc.w, 16);

    if (half == 0) {
        g_agg4[(size_t)warp * (D / 4) + slot] = acc;
    }
}

// ---------------------------------------------------------------------------
// K5: fused dual GEMM + bias + degree normalization.
//   out[n][o] = sum_k x[n][k]*Ws[o][k] + (sum_k agg[n][k]*Wn[o][k])/max(deg,1)
//             + bs[o] + bn[o]
// ---------------------------------------------------------------------------
__global__ __launch_bounds__(256) void sage_gemm_kernel(
    const float* __restrict__ x,
    const float* __restrict__ Ws, const float* __restrict__ bs,
    const float* __restrict__ Wn, const float* __restrict__ bn,
    float* __restrict__ out, int N)
{
    extern __shared__ float sh[];
    float* Wts  = sh;                 // [64][TP]
    float* Wtn  = sh + 64 * TP;       // [64][TP]
    float* xt   = sh + 2 * 64 * TP;   // [64][TP]  (x tile, then agg tile)
    float* bias = sh + 3 * 64 * TP;   // [64]

    const int tid = threadIdx.x;
    const float* agg = reinterpret_cast<const float*>(g_agg4);

    for (int i = tid; i < 64 * 64; i += 256) {
        int o = i >> 6, k = i & 63;
        Wts[k * TP + o] = Ws[i];
        Wtn[k * TP + o] = Wn[i];
    }
    if (tid < 64) bias[tid] = bs[tid] + bn[tid];

    const int to = tid & 15;
    const int tn = tid >> 4;
    const int node0 = blockIdx.x << 6;

    for (int i = tid; i < 64 * 64; i += 256) {
        int n = i >> 6, k = i & 63;
        int node = node0 + n;
        xt[k * TP + n] = (node < N) ? x[(size_t)node * D + k] : 0.f;
    }
    __syncthreads();

    float acc[4][4];
    #pragma unroll
    for (int i = 0; i < 4; i++)
        #pragma unroll
        for (int j = 0; j < 4; j++) acc[i][j] = 0.f;

    #pragma unroll
    for (int k = 0; k < 64; k++) {
        float4 a = *reinterpret_cast<const float4*>(&xt[k * TP + 4 * tn]);
        float4 w = *reinterpret_cast<const float4*>(&Wts[k * TP + 4 * to]);
        float av[4] = {a.x, a.y, a.z, a.w};
        float wv[4] = {w.x, w.y, w.z, w.w};
        #pragma unroll
        for (int i = 0; i < 4; i++)
            #pragma unroll
            for (int j = 0; j < 4; j++) acc[i][j] += av[i] * wv[j];
    }

    __syncthreads();
    for (int i = tid; i < 64 * 64; i += 256) {
        int n = i >> 6, k = i & 63;
        int node = node0 + n;
        xt[k * TP + n] = (node < N) ? agg[(size_t)node * D + k] : 0.f;
    }
    __syncthreads();

    float accn[4][4];
    #pragma unroll
    for (int i = 0; i < 4; i++)
        #pragma unroll
        for (int j = 0; j < 4; j++) accn[i][j] = 0.f;

    #pragma unroll
    for (int k = 0; k < 64; k++) {
        float4 a = *reinterpret_cast<const float4*>(&xt[k * TP + 4 * tn]);
        float4 w = *reinterpret_cast<const float4*>(&Wtn[k * TP + 4 * to]);
        float av[4] = {a.x, a.y, a.z, a.w};
        float wv[4] = {w.x, w.y, w.z, w.w};
        #pragma unroll
        for (int i = 0; i < 4; i++)
            #pragma unroll
            for (int j = 0; j < 4; j++) accn[i][j] += av[i] * wv[j];
    }

    float bj[4];
    #pragma unroll
    for (int j = 0; j < 4; j++) bj[j] = bias[4 * to + j];

    #pragma unroll
    for (int i = 0; i < 4; i++) {
        int node = node0 + 4 * tn + i;
        if (node < N) {
            float inv = 1.0f / fmaxf((float)g_cnt[node], 1.0f);
            float4 r;
            r.x = acc[i][0] + accn[i][0] * inv + bj[0];
            r.y = acc[i][1] + accn[i][1] * inv + bj[1];
            r.z = acc[i][2] + accn[i][2] * inv + bj[2];
            r.w = acc[i][3] + accn[i][3] * inv + bj[3];
            *reinterpret_cast<float4*>(&out[(size_t)node * D + 4 * to]) = r;
        }
    }
}

// ---------------------------------------------------------------------------
// Launch
// ---------------------------------------------------------------------------
extern "C" void kernel_launch(void* const* d_in, const int* in_sizes, int n_in,
                              void* d_out, int out_size) {
    const float* x  = (const float*)d_in[0];
    const int*   ei = (const int*)d_in[1];   // int64 reference -> int32 on device
    const float* Ws = (const float*)d_in[2];
    const float* bs = (const float*)d_in[3];
    const float* Wn = (const float*)d_in[4];
    const float* bn = (const float*)d_in[5];
    float*       out = (float*)d_out;

    const int N = in_sizes[0] / D;
    const int E = in_sizes[1] / 2;

    // 0) zero histogram counters
    void* cnt_ptr = nullptr;
    cudaGetSymbolAddress(&cnt_ptr, g_cnt);
    cudaMemsetAsync(cnt_ptr, 0, (size_t)N * sizeof(int));

    // 1) histogram of destination rows
    hist_kernel<<<(E + 255) / 256, 256>>>(ei, E, N);

    // 2) three-phase parallel exclusive scan -> g_off / g_cur
    const int nb = (N + 1023) / 1024;   // 49 for N=50000 (fits 64-wide scanB)
    scanA_kernel<<<nb, 1024>>>(N);
    scanB_kernel<<<1, 64>>>(nb);
    scanC_kernel<<<nb, 1024>>>(N);

    // 3) bucket cols by row
    fill_kernel<<<(E + 255) / 256, 256>>>(ei, E, N);

    // 4) gather-aggregate (warp per node)
    gather_kernel<<<(N * 32 + 255) / 256, 256>>>(x, N);

    // 5) fused dual GEMM epilogue
    {
        const int smem = (3 * 64 * TP + 64) * (int)sizeof(float);  // 52480 B
        cudaFuncSetAttribute(sage_gemm_kernel,
                             cudaFuncAttributeMaxDynamicSharedMemorySize, smem);
        sage_gemm_kernel<<<(N + 63) / 64, 256, smem>>>(x, Ws, bs, Wn, bn, out, N);
    }
}

// round 7
// speedup vs baseline: 1.8727x; 1.0198x over previous
#include <cuda_runtime.h>
#include <cstdint>

#define MAXN 50000
#define MAXE 800000
#define D 64
#define TP 68  // weight smem row pad (floats); 272 B, multiple of 16
#define XP 68  // x/agg tile row pad (floats)

// Scratch (device globals)
__device__ int g_cnt[MAXN];      // per-node in-degree
__device__ int g_off[MAXN + 1];  // CSR offsets
__device__ int g_cur[MAXN];      // fill cursors
__device__ int g_scol[MAXE];     // cols sorted by destination row
__device__ int g_blkSum[64];     // per-scan-block sums

// ---------------------------------------------------------------------------
// K1: histogram of destination rows
// ---------------------------------------------------------------------------
__global__ void hist_kernel(const int* __restrict__ ei, int E, int N) {
    int e = blockIdx.x * blockDim.x + threadIdx.x;
    if (e < E) {
        int r = min(max(ei[e], 0), N - 1);
        atomicAdd(&g_cnt[r], 1);
    }
}

// ---------------------------------------------------------------------------
// K2a: per-block sums of g_cnt (coalesced)
// ---------------------------------------------------------------------------
__global__ __launch_bounds__(1024) void scanA_kernel(int N) {
    __shared__ int warpSum[32];
    int i = blockIdx.x * 1024 + threadIdx.x;
    int v = (i < N) ? g_cnt[i] : 0;
    #pragma unroll
    for (int d = 16; d > 0; d >>= 1) v += __shfl_xor_sync(0xffffffff, v, d);
    if ((threadIdx.x & 31) == 0) warpSum[threadIdx.x >> 5] = v;
    __syncthreads();
    if (threadIdx.x < 32) {
        int s = warpSum[threadIdx.x];
        #pragma unroll
        for (int d = 16; d > 0; d >>= 1) s += __shfl_xor_sync(0xffffffff, s, d);
        if (threadIdx.x == 0) g_blkSum[blockIdx.x] = s;
    }
}

// ---------------------------------------------------------------------------
// K2b: block-local shuffle scan + (fused) scan of block sums -> g_off/g_cur
// ---------------------------------------------------------------------------
__global__ __launch_bounds__(1024) void scanC_kernel(int N, int nb) {
    __shared__ int blkS[64];
    __shared__ int warpSum[32];
    const int t = threadIdx.x;
    const int lane = t & 31;
    const int w = t >> 5;

    // fused scanB: inclusive Hillis over (<=64) block sums
    if (t < 64) blkS[t] = (t < nb) ? g_blkSum[t] : 0;
    __syncthreads();
    #pragma unroll
    for (int d = 1; d < 64; d <<= 1) {
        int u = (t < 64 && t >= d) ? blkS[t - d] : 0;
        __syncthreads();
        if (t < 64) blkS[t] += u;
        __syncthreads();
    }

    const int i = blockIdx.x * 1024 + t;
    const int v = (i < N) ? g_cnt[i] : 0;

    // warp inclusive scan
    int s = v;
    #pragma unroll
    for (int d = 1; d < 32; d <<= 1) {
        int u = __shfl_up_sync(0xffffffff, s, d);
        if (lane >= d) s += u;
    }
    if (lane == 31) warpSum[w] = s;
    __syncthreads();
    if (w == 0) {
        int s2 = warpSum[lane];
        #pragma unroll
        for (int d = 1; d < 32; d <<= 1) {
            int u = __shfl_up_sync(0xffffffff, s2, d);
            if (lane >= d) s2 += u;
        }
        warpSum[lane] = s2;
    }
    __syncthreads();

    int blockOff = (blockIdx.x > 0) ? blkS[blockIdx.x - 1] : 0;
    int incl = s + ((w > 0) ? warpSum[w - 1] : 0) + blockOff;
    int excl = incl - v;
    if (i < N) {
        g_off[i] = excl;
        g_cur[i] = excl;
        if (i == N - 1) g_off[N] = incl;
    }
}

// ---------------------------------------------------------------------------
// K3: fill CSR column array
// ---------------------------------------------------------------------------
__global__ void fill_kernel(const int* __restrict__ ei, int E, int N) {
    int e = blockIdx.x * blockDim.x + threadIdx.x;
    if (e < E) {
        int r = min(max(ei[e], 0), N - 1);
        int c = min(max(ei[E + e], 0), N - 1);
        int pos = atomicAdd(&g_cur[r], 1);
        g_scol[pos] = c;
    }
}

// ---------------------------------------------------------------------------
// K4: FUSED  self-GEMM -> in-smem CSR gather -> neighbor-GEMM -> epilogue.
// One block = 64 nodes x 64 outs. Tile xa is node-major [n][XP]:
//   phase 1: acc  = x_tile @ Ws^T          (a via 2-addr LDS broadcast)
//   gather : warp g handles nodes 8g..8g+7; 16 lanes x float4 over D,
//            half-warps cover alternating edges; writes rows of xa in place
//   phase 2: accn = agg_tile @ Wn^T
//   out = acc + accn/max(deg,1) + (bs+bn)
// ---------------------------------------------------------------------------
__global__ __launch_bounds__(256) void sage_fused_kernel(
    const float* __restrict__ x,
    const float* __restrict__ Ws, const float* __restrict__ bs,
    const float* __restrict__ Wn, const float* __restrict__ bn,
    float* __restrict__ out, int N)
{
    extern __shared__ float sh[];
    float* W1t  = sh;                       // [64][TP] Ws transposed: [k][o]
    float* W2t  = sh + 64 * TP;             // [64][TP] Wn transposed
    float* xa   = sh + 2 * 64 * TP;         // [64][XP] node-major tile
    float* bias = sh + 2 * 64 * TP + 64 * XP; // [64]

    const int tid  = threadIdx.x;
    const int lane = tid & 31;
    const int wrp  = tid >> 5;
    const float4* x4 = reinterpret_cast<const float4*>(x);

    // weights transposed into smem
    for (int i = tid; i < 64 * 64; i += 256) {
        int o = i >> 6, k = i & 63;
        W1t[k * TP + o] = Ws[i];
        W2t[k * TP + o] = Wn[i];
    }
    if (tid < 64) bias[tid] = bs[tid] + bn[tid];

    const int node0 = blockIdx.x << 6;

    // x tile: straight row-major copy (coalesced float4 both sides)
    for (int i = tid; i < 64 * 16; i += 256) {
        int n = i >> 4, k4 = i & 15;
        int node = node0 + n;
        float4 v = (node < N) ? __ldg(x4 + (size_t)node * 16 + k4)
                              : make_float4(0.f, 0.f, 0.f, 0.f);
        *reinterpret_cast<float4*>(&xa[n * XP + 4 * k4]) = v;
    }
    __syncthreads();

    const int to = tid & 15;   // outs  4*to..4*to+3
    const int tn = tid >> 4;   // nodes 4*tn..4*tn+3

    // ---- phase 1: self GEMM ----
    float acc[4][4];
    #pragma unroll
    for (int i = 0; i < 4; i++)
        #pragma unroll
        for (int j = 0; j < 4; j++) acc[i][j] = 0.f;

    #pragma unroll
    for (int k = 0; k < 64; k++) {
        float4 wv = *reinterpret_cast<const float4*>(&W1t[k * TP + 4 * to]);
        float a0 = xa[(4 * tn + 0) * XP + k];
        float a1 = xa[(4 * tn + 1) * XP + k];
        float a2 = xa[(4 * tn + 2) * XP + k];
        float a3 = xa[(4 * tn + 3) * XP + k];
        acc[0][0] += a0 * wv.x; acc[0][1] += a0 * wv.y; acc[0][2] += a0 * wv.z; acc[0][3] += a0 * wv.w;
        acc[1][0] += a1 * wv.x; acc[1][1] += a1 * wv.y; acc[1][2] += a1 * wv.z; acc[1][3] += a1 * wv.w;
        acc[2][0] += a2 * wv.x; acc[2][1] += a2 * wv.y; acc[2][2] += a2 * wv.z; acc[2][3] += a2 * wv.w;
        acc[3][0] += a3 * wv.x; acc[3][1] += a3 * wv.y; acc[3][2] += a3 * wv.z; acc[3][3] += a3 * wv.w;
    }
    __syncthreads();  // everyone done reading x tile

    // ---- gather phase: overwrite xa rows with neighbor sums ----
    {
        const int slot = lane & 15;  // float4 slot within D
        const int half = lane >> 4;  // alternating edges
        #pragma unroll
        for (int q = 0; q < 8; q++) {
            int ln = wrp * 8 + q;
            int node = node0 + ln;
            if (node < N) {
                int e   = g_off[node] + half;
                int end = g_off[node + 1];
                float4 s0 = make_float4(0.f, 0.f, 0.f, 0.f);
                float4 s1 = make_float4(0.f, 0.f, 0.f, 0.f);
                for (; e + 2 < end; e += 4) {  // 2 edges/iter per half (4 in flight/warp-half)
                    int c0 = g_scol[e];
                    int c1 = g_scol[e + 2];
                    float4 v0 = __ldg(x4 + (size_t)c0 * 16 + slot);
                    float4 v1 = __ldg(x4 + (size_t)c1 * 16 + slot);
                    s0.x += v0.x; s0.y += v0.y; s0.z += v0.z; s0.w += v0.w;
                    s1.x += v1.x; s1.y += v1.y; s1.z += v1.z; s1.w += v1.w;
                }
                if (e < end) {
                    int c = g_scol[e];
                    float4 v = __ldg(x4 + (size_t)c * 16 + slot);
                    s0.x += v.x; s0.y += v.y; s0.z += v.z; s0.w += v.w;
                }
                s0.x += s1.x; s0.y += s1.y; s0.z += s1.z; s0.w += s1.w;
                // combine the two halves
                s0.x += __shfl_xor_sync(0xffffffff, s0.x, 16);
                s0.y += __shfl_xor_sync(0xffffffff, s0.y, 16);
                s0.z += __shfl_xor_sync(0xffffffff, s0.z, 16);
                s0.w += __shfl_xor_sync(0xffffffff, s0.w, 16);
                if (half == 0) {
                    *reinterpret_cast<float4*>(&xa[ln * XP + 4 * slot]) = s0;
                }
            }
        }
    }
    __syncthreads();

    // ---- phase 2: neighbor GEMM ----
    float accn[4][4];
    #pragma unroll
    for (int i = 0; i < 4; i++)
        #pragma unroll
        for (int j = 0; j < 4; j++) accn[i][j] = 0.f;

    #pragma unroll
    for (int k = 0; k < 64; k++) {
        float4 wv = *reinterpret_cast<const float4*>(&W2t[k * TP + 4 * to]);
        float a0 = xa[(4 * tn + 0) * XP + k];
        float a1 = xa[(4 * tn + 1) * XP + k];
        float a2 = xa[(4 * tn + 2) * XP + k];
        float a3 = xa[(4 * tn + 3) * XP + k];
        accn[0][0] += a0 * wv.x; accn[0][1] += a0 * wv.y; accn[0][2] += a0 * wv.z; accn[0][3] += a0 * wv.w;
        accn[1][0] += a1 * wv.x; accn[1][1] += a1 * wv.y; accn[1][2] += a1 * wv.z; accn[1][3] += a1 * wv.w;
        accn[2][0] += a2 * wv.x; accn[2][1] += a2 * wv.y; accn[2][2] += a2 * wv.z; accn[2][3] += a2 * wv.w;
        accn[3][0] += a3 * wv.x; accn[3][1] += a3 * wv.y; accn[3][2] += a3 * wv.z; accn[3][3] += a3 * wv.w;
    }

    // ---- epilogue ----
    float bj[4];
    #pragma unroll
    for (int j = 0; j < 4; j++) bj[j] = bias[4 * to + j];

    #pragma unroll
    for (int i = 0; i < 4; i++) {
        int node = node0 + 4 * tn + i;
        if (node < N) {
            float inv = 1.0f / fmaxf((float)g_cnt[node], 1.0f);
            float4 r;
            r.x = acc[i][0] + accn[i][0] * inv + bj[0];
            r.y = acc[i][1] + accn[i][1] * inv + bj[1];
            r.z = acc[i][2] + accn[i][2] * inv + bj[2];
            r.w = acc[i][3] + accn[i][3] * inv + bj[3];
            *reinterpret_cast<float4*>(&out[(size_t)node * D + 4 * to]) = r;
        }
    }
}

// ---------------------------------------------------------------------------
// Launch
// ---------------------------------------------------------------------------
extern "C" void kernel_launch(void* const* d_in, const int* in_sizes, int n_in,
                              void* d_out, int out_size) {
    const float* x  = (const float*)d_in[0];
    const int*   ei = (const int*)d_in[1];   // int64 reference -> int32 on device
    const float* Ws = (const float*)d_in[2];
    const float* bs = (const float*)d_in[3];
    const float* Wn = (const float*)d_in[4];
    const float* bn = (const float*)d_in[5];
    float*       out = (float*)d_out;

    const int N = in_sizes[0] / D;
    const int E = in_sizes[1] / 2;

    // 0) zero histogram counters
    void* cnt_ptr = nullptr;
    cudaGetSymbolAddress(&cnt_ptr, g_cnt);
    cudaMemsetAsync(cnt_ptr, 0, (size_t)N * sizeof(int));

    // 1) histogram
    hist_kernel<<<(E + 255) / 256, 256>>>(ei, E, N);

    // 2) scan (A: block sums; C: shuffle scan with fused block-sum scan)
    const int nb = (N + 1023) / 1024;  // 49 for N=50000 (<=64)
    scanA_kernel<<<nb, 1024>>>(N);
    scanC_kernel<<<nb, 1024>>>(N, nb);

    // 3) bucket cols by destination row
    fill_kernel<<<(E + 255) / 256, 256>>>(ei, E, N);

    // 4) fused self-GEMM + gather + neighbor-GEMM + epilogue
    {
        const int smem = (2 * 64 * TP + 64 * XP + 64) * (int)sizeof(float);  // 52480 B
        cudaFuncSetAttribute(sage_fused_kernel,
                             cudaFuncAttributeMaxDynamicSharedMemorySize, smem);
        sage_fused_kernel<<<(N + 63) / 64, 256, smem>>>(x, Ws, bs, Wn, bn, out, N);
    }
}